// round 3
// baseline (speedup 1.0000x reference)
#include <cuda_runtime.h>
#include <cstdint>

#define BB 8
#define NN 2048
#define FF 128
#define UU 128

// Scratch (allocation-free rule: __device__ globals)
__device__ float g_T[BB * NN * UU];   // 8 MB: T = X@Wf + bf, pre-rounded to tf32
__device__ float g_a[BB * NN];        // a_j = T_j . w1
__device__ float g_e[BB * NN];        // e_j = exp(a_j - max_b a), tf32-rounded

__device__ __forceinline__ unsigned tf32_bits(float x) {
    unsigned r;
    asm("cvt.rna.tf32.f32 %0, %1;" : "=r"(r) : "f"(x));
    return r;
}
__device__ __forceinline__ float tf32_round(float x) {
    return __uint_as_float(tf32_bits(x));
}

__device__ __forceinline__ void cp16(void* smem, const void* gmem) {
    unsigned s = (unsigned)__cvta_generic_to_shared(smem);
    asm volatile("cp.async.cg.shared.global [%0], [%1], 16;" :: "r"(s), "l"(gmem));
}
__device__ __forceinline__ void cp_commit() {
    asm volatile("cp.async.commit_group;");
}
template <int N>
__device__ __forceinline__ void cp_wait() {
    asm volatile("cp.async.wait_group %0;" :: "n"(N));
}

// ---------------------------------------------------------------------------
// Kernel A: T[b,n,u] = tf32_round( X[b,n,:] @ Wf[:,u] + bf[u] )
// 512 blocks x 256 threads. Block: 32 rows x 128 u. Thread: 16 rows, 1 u.
// ---------------------------------------------------------------------------
__global__ void __launch_bounds__(256) k_feat(const float* __restrict__ X,
                                              const float* __restrict__ Wf,
                                              const float* __restrict__ bf,
                                              float* __restrict__ T) {
    __shared__ float xs[32][128];
    const int tid = threadIdx.x;
    const int u = tid & 127;
    const int rg = tid >> 7;  // 0..1 -> rows [rg*16, rg*16+16)
    const long base_row = (long)blockIdx.x * 32;

    const float4* Xv = (const float4*)(X + base_row * FF);
    float4* xsv = (float4*)xs;
    #pragma unroll
    for (int t = 0; t < 4; t++) xsv[tid + t * 256] = Xv[tid + t * 256];
    __syncthreads();

    float acc[16];
    const float bfu = bf[u];
    #pragma unroll
    for (int r = 0; r < 16; r++) acc[r] = bfu;

    #pragma unroll 4
    for (int f = 0; f < FF; f++) {
        const float w = Wf[f * UU + u];
        #pragma unroll
        for (int r = 0; r < 16; r++) acc[r] += xs[rg * 16 + r][f] * w;
    }
    #pragma unroll
    for (int r = 0; r < 16; r++)
        T[(base_row + rg * 16 + r) * UU + u] = tf32_round(acc[r]);
}

// ---------------------------------------------------------------------------
// Kernel B: a_j = T_j . w1   (w1 = Ws[0:128]).  One warp per row.
// ---------------------------------------------------------------------------
__global__ void __launch_bounds__(256) k_a(const float* __restrict__ T,
                                           const float* __restrict__ Ws,
                                           float* __restrict__ a) {
    const int gw = (blockIdx.x * blockDim.x + threadIdx.x) >> 5;
    const int lane = threadIdx.x & 31;
    if (gw >= BB * NN) return;
    const float4 v = ((const float4*)(T + (long)gw * UU))[lane];
    const float4 w = ((const float4*)Ws)[lane];
    float s = v.x * w.x + v.y * w.y + v.z * w.z + v.w * w.w;
    #pragma unroll
    for (int o = 16; o; o >>= 1) s += __shfl_xor_sync(0xFFFFFFFFu, s, o);
    if (lane == 0) a[gw] = s;
}

// ---------------------------------------------------------------------------
// Kernel C: per-batch max over a, then e_j = tf32(exp(a_j - max)).
// ---------------------------------------------------------------------------
__global__ void __launch_bounds__(256) k_e(const float* __restrict__ a,
                                           float* __restrict__ e) {
    __shared__ float red[8];
    __shared__ float mshared;
    const int b = blockIdx.x, tid = threadIdx.x;
    const float* ab = a + b * NN;
    float m = -1e30f;
    for (int j = tid; j < NN; j += 256) m = fmaxf(m, ab[j]);
    #pragma unroll
    for (int o = 16; o; o >>= 1) m = fmaxf(m, __shfl_xor_sync(0xFFFFFFFFu, m, o));
    if ((tid & 31) == 0) red[tid >> 5] = m;
    __syncthreads();
    if (tid == 0) {
        float mm = red[0];
        #pragma unroll
        for (int i = 1; i < 8; i++) mm = fmaxf(mm, red[i]);
        mshared = mm;
    }
    __syncthreads();
    const float mx = mshared;
    for (int j = tid; j < NN; j += 256)
        e[b * NN + j] = tf32_round(expf(ab[j] - mx));
}

// ---------------------------------------------------------------------------
// Kernel D: out[b,i,:] = (sum_j mask_ij * e_j * T_j) / (sum_j mask_ij * e_j)
// Masked batched GEMM, tf32 mma.sync, cp.async 2-stage pipeline.
// CTA tile: 128 rows x 128 cols, K-chunk 32. Grid (16, 8), 256 threads.
// ---------------------------------------------------------------------------
#define N_KTILES (NN / 32)

struct AttnSmem {
    int   adjs[2][128][36];    // pad 36 ints: conflict-light fragment reads
    float Ds[2][32][132];      // B tile [k][u], pad 132
    float es[2][32];
    float denoms[128];
};
#define ATTN_SMEM_BYTES sizeof(AttnSmem)

__global__ void __launch_bounds__(256) k_attn(const int* __restrict__ adj,
                                              const float* __restrict__ Tm,
                                              const float* __restrict__ e,
                                              float* __restrict__ out) {
    extern __shared__ char smem_raw[];
    AttnSmem& sm = *reinterpret_cast<AttnSmem*>(smem_raw);

    const int b = blockIdx.y;
    const long i0 = (long)blockIdx.x * 128;
    const int tid = threadIdx.x;
    const int lane = tid & 31;
    const int w = tid >> 5;
    const int wr = w >> 1;   // 0..3 : rows [wr*32, wr*32+32)
    const int wc = w & 1;    // 0..1 : cols [wc*64, wc*64+64)
    const int tg = lane & 3;   // thread-in-group (k / col pairs)
    const int gid = lane >> 2; // group id (rows / cols)

    float c[2][8][4];
    #pragma unroll
    for (int mt = 0; mt < 2; mt++)
        #pragma unroll
        for (int nt = 0; nt < 8; nt++)
            #pragma unroll
            for (int q = 0; q < 4; q++) c[mt][nt][q] = 0.f;

    if (tid < 128) sm.denoms[tid] = 0.f;

    const int* adjBase = adj + ((long)b * NN + i0) * NN;
    const float* Tb = Tm + (long)b * NN * UU;
    const float* eb = e + (long)b * NN;

    // ---- async tile issue ----
    auto issue_tile = [&](int t) {
        const int bufi = t & 1;
        const int k0 = t * 32;
        // adjacency tile: 128 rows x 32 ints = 1024 x 16B
        #pragma unroll
        for (int q = 0; q < 4; q++) {
            const int idx = tid + q * 256;
            const int i = idx >> 3, q4 = idx & 7;
            cp16(&sm.adjs[bufi][i][q4 * 4],
                 adjBase + (long)i * NN + k0 + q4 * 4);
        }
        // D tile: 32 x 128 floats = 1024 x 16B (already tf32-rounded)
        #pragma unroll
        for (int q = 0; q < 4; q++) {
            const int idx = tid + q * 256;
            const int kk = idx >> 5, u4 = idx & 31;
            cp16(&sm.Ds[bufi][kk][u4 * 4],
                 Tb + (long)(k0 + kk) * UU + u4 * 4);
        }
        // e slice: 32 floats = 8 x 16B
        if (tid < 8) cp16(&sm.es[bufi][tid * 4], eb + k0 + tid * 4);
        cp_commit();
    };

    issue_tile(0);

    for (int t = 0; t < N_KTILES; t++) {
        const int cur = t & 1;
        if (t + 1 < N_KTILES) {
            issue_tile(t + 1);
            cp_wait<1>();
        } else {
            cp_wait<0>();
        }
        __syncthreads();   // tile t visible to all

        const int (*adjs)[36] = sm.adjs[cur];
        const float (*Ds)[132] = sm.Ds[cur];
        const float* es = sm.es[cur];

        // denominator partials (threads 0..127, one row each)
        if (tid < 128) {
            float d = 0.f;
            #pragma unroll
            for (int kk = 0; kk < 32; kk++)
                d += adjs[tid][kk] ? es[kk] : 0.f;
            sm.denoms[tid] += d;
        }

        // tf32 mma over the 32-deep chunk (4 k-steps of 8)
        #pragma unroll
        for (int s = 0; s < 4; s++) {
            const int kA0 = s * 8 + tg;
            const unsigned e0 = __float_as_uint(es[kA0]);
            const unsigned e1 = __float_as_uint(es[kA0 + 4]);
            unsigned av[2][4];
            #pragma unroll
            for (int mt = 0; mt < 2; mt++) {
                const int ri = wr * 32 + mt * 16 + gid;
                av[mt][0] = adjs[ri][kA0]         ? e0 : 0u;
                av[mt][1] = adjs[ri + 8][kA0]     ? e0 : 0u;
                av[mt][2] = adjs[ri][kA0 + 4]     ? e1 : 0u;
                av[mt][3] = adjs[ri + 8][kA0 + 4] ? e1 : 0u;
            }
            #pragma unroll
            for (int nt = 0; nt < 8; nt++) {
                const int ncol = wc * 64 + nt * 8 + gid;
                const unsigned b0 = __float_as_uint(Ds[s * 8 + tg][ncol]);
                const unsigned b1 = __float_as_uint(Ds[s * 8 + tg + 4][ncol]);
                #pragma unroll
                for (int mt = 0; mt < 2; mt++) {
                    asm volatile(
                        "mma.sync.aligned.m16n8k8.row.col.f32.tf32.tf32.f32 "
                        "{%0,%1,%2,%3}, {%4,%5,%6,%7}, {%8,%9}, {%0,%1,%2,%3};"
                        : "+f"(c[mt][nt][0]), "+f"(c[mt][nt][1]),
                          "+f"(c[mt][nt][2]), "+f"(c[mt][nt][3])
                        : "r"(av[mt][0]), "r"(av[mt][1]),
                          "r"(av[mt][2]), "r"(av[mt][3]),
                          "r"(b0), "r"(b1));
                }
            }
        }
        __syncthreads();   // all reads of buffer `cur` done before it is refilled
    }

    // epilogue: divide by denominator, write out
    #pragma unroll
    for (int mt = 0; mt < 2; mt++) {
        const int rloc0 = wr * 32 + mt * 16 + gid;
        #pragma unroll
        for (int half = 0; half < 2; half++) {
            const int rloc = rloc0 + half * 8;
            float dn = sm.denoms[rloc];
            dn = (dn != 0.f) ? dn : 1.f;
            const float inv = 1.f / dn;
            const long row = i0 + rloc;
            float* orow = out + ((long)b * NN + row) * UU;
            #pragma unroll
            for (int nt = 0; nt < 8; nt++) {
                const int col = wc * 64 + nt * 8 + tg * 2;
                float2 v;
                v.x = c[mt][nt][half * 2 + 0] * inv;
                v.y = c[mt][nt][half * 2 + 1] * inv;
                *(float2*)(orow + col) = v;
            }
        }
    }
}

// ---------------------------------------------------------------------------
extern "C" void kernel_launch(void* const* d_in, const int* in_sizes, int n_in,
                              void* d_out, int out_size) {
    const float* X   = (const float*)d_in[0];  // [B,N,F]
    const int*   adj = (const int*)  d_in[1];  // [B,N,N]
    const float* Wf  = (const float*)d_in[2];  // [F,U]
    const float* bf  = (const float*)d_in[3];  // [U]
    const float* Ws  = (const float*)d_in[4];  // [2U]
    // d_in[5] = bs (scalar): constant along softmax axis -> cancels. w2 likewise.
    float* out = (float*)d_out;

    float *T, *a, *e;
    cudaGetSymbolAddress((void**)&T, g_T);
    cudaGetSymbolAddress((void**)&a, g_a);
    cudaGetSymbolAddress((void**)&e, g_e);

    static bool attr_set = false;
    if (!attr_set) {
        cudaFuncSetAttribute(k_attn, cudaFuncAttributeMaxDynamicSharedMemorySize,
                             (int)ATTN_SMEM_BYTES);
        attr_set = true;
    }

    k_feat<<<512, 256>>>(X, Wf, bf, T);
    k_a<<<2048, 256>>>(T, Ws, a);
    k_e<<<BB, 256>>>(a, e);
    dim3 grid(16, BB);
    k_attn<<<grid, 256, ATTN_SMEM_BYTES>>>(adj, T, e, out);
}

// round 4
// speedup vs baseline: 1.3912x; 1.3912x over previous
#include <cuda_runtime.h>
#include <cstdint>

#define BB 8
#define NN 2048
#define FF 128
#define UU 128

// Scratch (allocation-free rule: __device__ globals)
__device__ float g_T[BB * NN * UU];   // 8 MB: T = X@Wf + bf, tf32-rounded
__device__ float g_a[BB * NN];        // a_j = T_j . w1
__device__ float g_e[BB * NN];        // e_j = exp(a_j - max_b a), tf32-rounded
__device__ float g_Wfr[FF * UU];      // Wf pre-rounded to tf32

__device__ __forceinline__ unsigned tf32_bits(float x) {
    unsigned r;
    asm("cvt.rna.tf32.f32 %0, %1;" : "=r"(r) : "f"(x));
    return r;
}
__device__ __forceinline__ float tf32_round(float x) {
    return __uint_as_float(tf32_bits(x));
}

__device__ __forceinline__ void cp16(void* smem, const void* gmem) {
    unsigned s = (unsigned)__cvta_generic_to_shared(smem);
    asm volatile("cp.async.cg.shared.global [%0], [%1], 16;" :: "r"(s), "l"(gmem));
}
__device__ __forceinline__ void cp_commit() {
    asm volatile("cp.async.commit_group;");
}
template <int N>
__device__ __forceinline__ void cp_wait() {
    asm volatile("cp.async.wait_group %0;" :: "n"(N));
}
__device__ __forceinline__ void bar_sync(int id, int cnt) {
    asm volatile("bar.sync %0, %1;" :: "r"(id), "r"(cnt) : "memory");
}

// ---------------------------------------------------------------------------
// Kernel W: pre-round Wf to tf32.
// ---------------------------------------------------------------------------
__global__ void k_wf(const float* __restrict__ Wf, float* __restrict__ Wfr) {
    const int i = blockIdx.x * blockDim.x + threadIdx.x;
    if (i < FF * UU) Wfr[i] = tf32_round(Wf[i]);
}

// ---------------------------------------------------------------------------
// Kernel A: T = tf32_round( X @ Wfr + bf )  as tf32 mma GEMM.
// Grid 128 CTAs (128 rows each), 256 threads, warp tile 32x64, K=128 (4 tiles).
// ---------------------------------------------------------------------------
struct FeatSmem {
    float xs[2][128][36];   // A tile (X), pad 36
    float ds[2][32][136];   // B tile (Wfr), pad 136: conflict-free b-frags
};
#define FEAT_SMEM_BYTES sizeof(FeatSmem)

__global__ void __launch_bounds__(256) k_feat(const float* __restrict__ X,
                                              const float* __restrict__ Wfr,
                                              const float* __restrict__ bf,
                                              float* __restrict__ T) {
    extern __shared__ char smem_raw[];
    FeatSmem& sm = *reinterpret_cast<FeatSmem*>(smem_raw);

    const long i0 = (long)blockIdx.x * 128;
    const int tid = threadIdx.x;
    const int lane = tid & 31;
    const int w = tid >> 5;
    const int wr = w >> 1, wc = w & 1;
    const int tg = lane & 3, gid = lane >> 2;

    float c[2][8][4];
    #pragma unroll
    for (int mt = 0; mt < 2; mt++)
        #pragma unroll
        for (int nt = 0; nt < 8; nt++)
            #pragma unroll
            for (int q = 0; q < 4; q++) c[mt][nt][q] = 0.f;

    auto issue_tile = [&](int t) {
        const int bufi = t & 1;
        const int k0 = t * 32;
        #pragma unroll
        for (int q = 0; q < 4; q++) {
            const int idx = tid + q * 256;
            const int i = idx >> 3, q4 = idx & 7;
            cp16(&sm.xs[bufi][i][q4 * 4], X + (i0 + i) * FF + k0 + q4 * 4);
        }
        #pragma unroll
        for (int q = 0; q < 4; q++) {
            const int idx = tid + q * 256;
            const int kk = idx >> 5, u4 = idx & 31;
            cp16(&sm.ds[bufi][kk][u4 * 4], Wfr + (long)(k0 + kk) * UU + u4 * 4);
        }
        cp_commit();
    };

    issue_tile(0);
    for (int t = 0; t < 4; t++) {
        const int cur = t & 1;
        if (t + 1 < 4) { issue_tile(t + 1); cp_wait<1>(); }
        else           { cp_wait<0>(); }
        __syncthreads();

        const float (*xs)[36] = sm.xs[cur];
        const float (*Ds)[136] = sm.ds[cur];

        #pragma unroll
        for (int s = 0; s < 4; s++) {
            const int kA0 = s * 8 + tg;
            unsigned av[2][4];
            #pragma unroll
            for (int mt = 0; mt < 2; mt++) {
                const int ri = wr * 32 + mt * 16 + gid;
                av[mt][0] = tf32_bits(xs[ri][kA0]);
                av[mt][1] = tf32_bits(xs[ri + 8][kA0]);
                av[mt][2] = tf32_bits(xs[ri][kA0 + 4]);
                av[mt][3] = tf32_bits(xs[ri + 8][kA0 + 4]);
            }
            #pragma unroll
            for (int nt = 0; nt < 8; nt++) {
                const int ncol = wc * 64 + nt * 8 + gid;
                const unsigned b0 = __float_as_uint(Ds[s * 8 + tg][ncol]);
                const unsigned b1 = __float_as_uint(Ds[s * 8 + tg + 4][ncol]);
                #pragma unroll
                for (int mt = 0; mt < 2; mt++) {
                    asm volatile(
                        "mma.sync.aligned.m16n8k8.row.col.f32.tf32.tf32.f32 "
                        "{%0,%1,%2,%3}, {%4,%5,%6,%7}, {%8,%9}, {%0,%1,%2,%3};"
                        : "+f"(c[mt][nt][0]), "+f"(c[mt][nt][1]),
                          "+f"(c[mt][nt][2]), "+f"(c[mt][nt][3])
                        : "r"(av[mt][0]), "r"(av[mt][1]),
                          "r"(av[mt][2]), "r"(av[mt][3]),
                          "r"(b0), "r"(b1));
                }
            }
        }
        __syncthreads();
    }

    // epilogue: + bf, tf32 round, store
    #pragma unroll
    for (int mt = 0; mt < 2; mt++) {
        const int rloc0 = wr * 32 + mt * 16 + gid;
        #pragma unroll
        for (int half = 0; half < 2; half++) {
            const int rloc = rloc0 + half * 8;
            float* orow = T + (i0 + rloc) * UU;
            #pragma unroll
            for (int nt = 0; nt < 8; nt++) {
                const int col = wc * 64 + nt * 8 + tg * 2;
                float2 v;
                v.x = tf32_round(c[mt][nt][half * 2 + 0] + bf[col]);
                v.y = tf32_round(c[mt][nt][half * 2 + 1] + bf[col + 1]);
                *(float2*)(orow + col) = v;
            }
        }
    }
}

// ---------------------------------------------------------------------------
// Kernel B: a_j = T_j . w1   (w1 = Ws[0:128]).  One warp per row.
// ---------------------------------------------------------------------------
__global__ void __launch_bounds__(256) k_a(const float* __restrict__ T,
                                           const float* __restrict__ Ws,
                                           float* __restrict__ a) {
    const int gw = (blockIdx.x * blockDim.x + threadIdx.x) >> 5;
    const int lane = threadIdx.x & 31;
    if (gw >= BB * NN) return;
    const float4 v = ((const float4*)(T + (long)gw * UU))[lane];
    const float4 w = ((const float4*)Ws)[lane];
    float s = v.x * w.x + v.y * w.y + v.z * w.z + v.w * w.w;
    #pragma unroll
    for (int o = 16; o; o >>= 1) s += __shfl_xor_sync(0xFFFFFFFFu, s, o);
    if (lane == 0) a[gw] = s;
}

// ---------------------------------------------------------------------------
// Kernel C: per-batch max over a, then e_j = tf32(exp(a_j - max)).
// ---------------------------------------------------------------------------
__global__ void __launch_bounds__(256) k_e(const float* __restrict__ a,
                                           float* __restrict__ e) {
    __shared__ float red[8];
    __shared__ float mshared;
    const int b = blockIdx.x, tid = threadIdx.x;
    const float* ab = a + b * NN;
    float m = -1e30f;
    for (int j = tid; j < NN; j += 256) m = fmaxf(m, ab[j]);
    #pragma unroll
    for (int o = 16; o; o >>= 1) m = fmaxf(m, __shfl_xor_sync(0xFFFFFFFFu, m, o));
    if ((tid & 31) == 0) red[tid >> 5] = m;
    __syncthreads();
    if (tid == 0) {
        float mm = red[0];
        #pragma unroll
        for (int i = 1; i < 8; i++) mm = fmaxf(mm, red[i]);
        mshared = mm;
    }
    __syncthreads();
    const float mx = mshared;
    for (int j = tid; j < NN; j += 256)
        e[b * NN + j] = tf32_round(expf(ab[j] - mx));
}

// ---------------------------------------------------------------------------
// Kernel D: out[b,i,:] = (sum_j mask_ij e_j T_j) / (sum_j mask_ij e_j)
// 512 threads = 2 independent 8-warp groups, each covering half of K with its
// own 3-stage cp.async pipeline (named barriers). Merge via smem at the end.
// Grid (16, 8). CTA tile: 128 rows x 128 cols; K-chunk 32, 32 tiles per group.
// ---------------------------------------------------------------------------
#define KT_PER_GROUP 32

struct AttnSmem {
    int   adjs[2][3][128][36];   // [grp][stage]: 110592 B
    float Ds[2][3][32][136];     // [grp][stage]: 104448 B (pad 136: no conflicts)
    float es[2][3][32];
    float den[2][128];
};
#define ATTN_SMEM_BYTES sizeof(AttnSmem)

__global__ void __launch_bounds__(512) k_attn(const int* __restrict__ adj,
                                              const float* __restrict__ Tm,
                                              const float* __restrict__ e,
                                              float* __restrict__ out) {
    extern __shared__ char smem_raw[];
    AttnSmem& sm = *reinterpret_cast<AttnSmem*>(smem_raw);

    const int b = blockIdx.y;
    const long i0 = (long)blockIdx.x * 128;
    const int tid = threadIdx.x;
    const int g = tid >> 8;          // group 0/1
    const int ltid = tid & 255;      // local tid within group
    const int lane = ltid & 31;
    const int w = ltid >> 5;
    const int wr = w >> 1;           // 0..3 : rows [wr*32, +32)
    const int wc = w & 1;            // 0..1 : cols [wc*64, +64)
    const int tg = lane & 3;
    const int gid = lane >> 2;
    const int kbase = g * (NN / 2);
    const int barid = g + 1;

    float c[2][8][4];
    #pragma unroll
    for (int mt = 0; mt < 2; mt++)
        #pragma unroll
        for (int nt = 0; nt < 8; nt++)
            #pragma unroll
            for (int q = 0; q < 4; q++) c[mt][nt][q] = 0.f;

    if (ltid < 128) sm.den[g][ltid] = 0.f;   // only thread ltid accumulates it

    const int* adjBase = adj + ((long)b * NN + i0) * NN + kbase;
    const float* Tb = Tm + ((long)b * NN + kbase) * UU;
    const float* eb = e + (long)b * NN + kbase;

    auto issue_tile = [&](int t) {
        const int st = t % 3;
        const int k0 = t * 32;
        #pragma unroll
        for (int q = 0; q < 4; q++) {
            const int idx = ltid + q * 256;
            const int i = idx >> 3, q4 = idx & 7;
            cp16(&sm.adjs[g][st][i][q4 * 4], adjBase + (long)i * NN + k0 + q4 * 4);
        }
        #pragma unroll
        for (int q = 0; q < 4; q++) {
            const int idx = ltid + q * 256;
            const int kk = idx >> 5, u4 = idx & 31;
            cp16(&sm.Ds[g][st][kk][u4 * 4], Tb + (long)(k0 + kk) * UU + u4 * 4);
        }
        if (ltid < 8) cp16(&sm.es[g][st][ltid * 4], eb + k0 + ltid * 4);
        cp_commit();
    };

    issue_tile(0);
    issue_tile(1);

    for (int t = 0; t < KT_PER_GROUP; t++) {
        const int cur = t % 3;
        if (t + 2 < KT_PER_GROUP) { issue_tile(t + 2); cp_wait<2>(); }
        else if (t + 1 < KT_PER_GROUP) { cp_wait<1>(); }
        else { cp_wait<0>(); }
        bar_sync(barid, 256);        // tile t visible to the whole group

        const int (*adjs)[36] = sm.adjs[g][cur];
        const float (*Ds)[136] = sm.Ds[g][cur];
        const float* es = sm.es[g][cur];

        if (ltid < 128) {
            float d = 0.f;
            #pragma unroll
            for (int kk = 0; kk < 32; kk++)
                d += adjs[ltid][kk] ? es[kk] : 0.f;
            sm.den[g][ltid] += d;
        }

        #pragma unroll
        for (int s = 0; s < 4; s++) {
            const int kA0 = s * 8 + tg;
            const unsigned e0 = __float_as_uint(es[kA0]);
            const unsigned e1 = __float_as_uint(es[kA0 + 4]);
            unsigned av[2][4];
            #pragma unroll
            for (int mt = 0; mt < 2; mt++) {
                const int ri = wr * 32 + mt * 16 + gid;
                av[mt][0] = adjs[ri][kA0]         ? e0 : 0u;
                av[mt][1] = adjs[ri + 8][kA0]     ? e0 : 0u;
                av[mt][2] = adjs[ri][kA0 + 4]     ? e1 : 0u;
                av[mt][3] = adjs[ri + 8][kA0 + 4] ? e1 : 0u;
            }
            #pragma unroll
            for (int nt = 0; nt < 8; nt++) {
                const int ncol = wc * 64 + nt * 8 + gid;
                const unsigned b0 = __float_as_uint(Ds[s * 8 + tg][ncol]);
                const unsigned b1 = __float_as_uint(Ds[s * 8 + tg + 4][ncol]);
                #pragma unroll
                for (int mt = 0; mt < 2; mt++) {
                    asm volatile(
                        "mma.sync.aligned.m16n8k8.row.col.f32.tf32.tf32.f32 "
                        "{%0,%1,%2,%3}, {%4,%5,%6,%7}, {%8,%9}, {%0,%1,%2,%3};"
                        : "+f"(c[mt][nt][0]), "+f"(c[mt][nt][1]),
                          "+f"(c[mt][nt][2]), "+f"(c[mt][nt][3])
                        : "r"(av[mt][0]), "r"(av[mt][1]),
                          "r"(av[mt][2]), "r"(av[mt][3]),
                          "r"(b0), "r"(b1));
                }
            }
        }
        bar_sync(barid, 256);        // reads of buffer `cur` done before refill
    }

    // ---- merge the two K-halves via smem (overlay Csum on adjs region) ----
    __syncthreads();                 // both groups done with all staging buffers
    float (*Csum)[132] = reinterpret_cast<float(*)[132]>(&sm.adjs[0][0][0][0]);

    if (g == 1) {
        #pragma unroll
        for (int mt = 0; mt < 2; mt++) {
            const int rloc0 = wr * 32 + mt * 16 + gid;
            #pragma unroll
            for (int half = 0; half < 2; half++) {
                const int rloc = rloc0 + half * 8;
                #pragma unroll
                for (int nt = 0; nt < 8; nt++) {
                    const int col = wc * 64 + nt * 8 + tg * 2;
                    float2 v;
                    v.x = c[mt][nt][half * 2 + 0];
                    v.y = c[mt][nt][half * 2 + 1];
                    *(float2*)&Csum[rloc][col] = v;
                }
            }
        }
    }
    __syncthreads();

    if (g == 0) {
        #pragma unroll
        for (int mt = 0; mt < 2; mt++) {
            const int rloc0 = wr * 32 + mt * 16 + gid;
            #pragma unroll
            for (int half = 0; half < 2; half++) {
                const int rloc = rloc0 + half * 8;
                float dn = sm.den[0][rloc] + sm.den[1][rloc];
                dn = (dn != 0.f) ? dn : 1.f;
                const float inv = 1.f / dn;
                float* orow = out + ((long)b * NN + i0 + rloc) * UU;
                #pragma unroll
                for (int nt = 0; nt < 8; nt++) {
                    const int col = wc * 64 + nt * 8 + tg * 2;
                    const float2 p = *(const float2*)&Csum[rloc][col];
                    float2 v;
                    v.x = (c[mt][nt][half * 2 + 0] + p.x) * inv;
                    v.y = (c[mt][nt][half * 2 + 1] + p.y) * inv;
                    *(float2*)(orow + col) = v;
                }
            }
        }
    }
}

// ---------------------------------------------------------------------------
extern "C" void kernel_launch(void* const* d_in, const int* in_sizes, int n_in,
                              void* d_out, int out_size) {
    const float* X   = (const float*)d_in[0];  // [B,N,F]
    const int*   adj = (const int*)  d_in[1];  // [B,N,N]
    const float* Wf  = (const float*)d_in[2];  // [F,U]
    const float* bf  = (const float*)d_in[3];  // [U]
    const float* Ws  = (const float*)d_in[4];  // [2U]
    // d_in[5] = bs: constant along softmax axis -> cancels. w2 likewise unused.
    float* out = (float*)d_out;

    float *T, *a, *e, *Wfr;
    cudaGetSymbolAddress((void**)&T, g_T);
    cudaGetSymbolAddress((void**)&a, g_a);
    cudaGetSymbolAddress((void**)&e, g_e);
    cudaGetSymbolAddress((void**)&Wfr, g_Wfr);

    cudaFuncSetAttribute(k_attn, cudaFuncAttributeMaxDynamicSharedMemorySize,
                         (int)ATTN_SMEM_BYTES);
    cudaFuncSetAttribute(k_feat, cudaFuncAttributeMaxDynamicSharedMemorySize,
                         (int)FEAT_SMEM_BYTES);

    k_wf<<<(FF * UU + 255) / 256, 256>>>(Wf, Wfr);
    k_feat<<<128, 256, FEAT_SMEM_BYTES>>>(X, Wfr, bf, T);
    k_a<<<2048, 256>>>(T, Ws, a);
    k_e<<<BB, 256>>>(a, e);
    dim3 grid(16, BB);
    k_attn<<<grid, 512, ATTN_SMEM_BYTES>>>(adj, T, e, out);
}